// round 13
// baseline (speedup 1.0000x reference)
#include <cuda_runtime.h>
#include <math.h>

// Problem constants: B=4, n=4096 points, m=512 triangles.
#define BATCH 4
#define NPTS  4096
#define MTRI  512
#define BN    (BATCH * NPTS)   // 16384

// Decomposition: 128-thread CTAs (4 warps), 16 points/CTA, grid = 1024.
//   chunk = tid & 31 (32 triangle chunks), grp = tid >> 5 (4 groups x 4 pts).
//   Each thread: 4 points = 2 packed f32x2 pairs x 16 triangles.
//
// NEW vs round 12: triangles staged in smem as BROADCAST float2 pairs (v,v),
// with A rows PRE-NEGATED (-a,-a). The per-triangle setup then runs entirely
// in packed registers from 9 LDS.64 loads — eliminating the 16 pk2(x,x)
// broadcast-MOV sequences per triangle. Only the 4 reciprocals go through a
// scalar MUFU (extract lo -> rcp -> repack).
//
// Packed-pair candidate-min evaluation (fma.rn.f32x2 path):
//   dist^2 = min(seg_ab, seg_ac, seg_bc, inside ? face : +inf)
// Region code recomputed reference-exactly for the winning triangle only.

typedef unsigned long long ull;

__device__ __forceinline__ ull pk2(float lo, float hi) {
    ull r;
    asm("mov.b64 %0, {%1, %2};" : "=l"(r) : "f"(lo), "f"(hi));
    return r;
}
__device__ __forceinline__ void up2(ull v, float& lo, float& hi) {
    asm("mov.b64 {%0, %1}, %2;" : "=f"(lo), "=f"(hi) : "l"(v));
}
__device__ __forceinline__ float lo2(ull v) {
    float lo;
    asm("{ .reg .f32 hi; mov.b64 {%0, hi}, %1; }" : "=f"(lo) : "l"(v));
    return lo;
}
__device__ __forceinline__ ull fma2_(ull a, ull b, ull c) {
    ull r;
    asm("fma.rn.f32x2 %0, %1, %2, %3;" : "=l"(r) : "l"(a), "l"(b), "l"(c));
    return r;
}
__device__ __forceinline__ ull mul2_(ull a, ull b) {
    ull r;
    asm("mul.rn.f32x2 %0, %1, %2;" : "=l"(r) : "l"(a), "l"(b));
    return r;
}
__device__ __forceinline__ ull add2_(ull a, ull b) {
    ull r;
    asm("add.rn.f32x2 %0, %1, %2;" : "=l"(r) : "l"(a), "l"(b));
    return r;
}
__device__ __forceinline__ float frcp(float x) {
    float r;
    asm("rcp.approx.f32 %0, %1;" : "=f"(r) : "f"(x));
    return r;
}
// clamp both components of a packed value to [-1, 0]
__device__ __forceinline__ ull clampn2(ull v) {
    float lo, hi;
    up2(v, lo, hi);
    lo = fminf(fmaxf(lo, -1.f), 0.f);
    hi = fminf(fmaxf(hi, -1.f), 0.f);
    return pk2(lo, hi);
}

__device__ int region_of(float px, float py, float pz,
                         float ax, float ay, float az,
                         float bx, float by, float bz,
                         float cx, float cy, float cz)
{
    const float abx = bx - ax, aby = by - ay, abz = bz - az;
    const float acx = cx - ax, acy = cy - ay, acz = cz - az;
    const float apx = px - ax, apy = py - ay, apz = pz - az;
    const float bpx = px - bx, bpy = py - by, bpz = pz - bz;
    const float cpx = px - cx, cpy = py - cy, cpz = pz - cz;
    const float d1 = abx * apx + aby * apy + abz * apz;
    const float d2 = acx * apx + acy * apy + acz * apz;
    const float d3 = abx * bpx + aby * bpy + abz * bpz;
    const float d4 = acx * bpx + acy * bpy + acz * bpz;
    const float d5 = abx * cpx + aby * cpy + abz * cpz;
    const float d6 = acx * cpx + acy * cpy + acz * cpz;
    const float vc = d1 * d4 - d3 * d2;
    const float vb = d5 * d2 - d1 * d6;
    const float va = d3 * d6 - d5 * d4;
    if (d1 <= 0.f && d2 <= 0.f) return 0;
    if (d3 >= 0.f && d4 <= d3) return 1;
    if (vc <= 0.f && d1 >= 0.f && d3 <= 0.f) return 3;
    if (d6 >= 0.f && d5 <= d6) return 2;
    if (vb <= 0.f && d2 >= 0.f && d6 <= 0.f) return 4;
    if (va <= 0.f && (d4 - d3) >= 0.f && (d5 - d6) >= 0.f) return 5;
    return 6;
}

__global__ void __launch_bounds__(128, 6)
tridist_kernel(const float* __restrict__ xyz,
               const float* __restrict__ tri1,
               const float* __restrict__ tri2,
               const float* __restrict__ tri3,
               float* __restrict__ out)
{
    // Broadcast pairs: rows 0-2 = (-ax,-ax)(-ay,-ay)(-az,-az),
    //                  rows 3-5 = b, rows 6-8 = c.  36 KB.
    __shared__ float2 smb[9][MTRI];
    __shared__ float  sp[48];        // 16 points * 3

    const int b     = blockIdx.x >> 8;
    const int blk   = blockIdx.x & 255;
    const int pbase = b * NPTS + blk * 16;

    // Stage triangles (float4 loads, broadcast-pair scatter into smem).
    {
        const float4* t1 = (const float4*)(tri1 + b * MTRI * 3);
        const float4* t2 = (const float4*)(tri2 + b * MTRI * 3);
        const float4* t3 = (const float4*)(tri3 + b * MTRI * 3);
        #pragma unroll
        for (int it = 0; it < 3; ++it) {
            const int i4 = it * 128 + threadIdx.x;   // 0..383
            float4 v1 = t1[i4], v2 = t2[i4], v3 = t3[i4];
            const int base = i4 * 4;
            float f1[4] = {v1.x, v1.y, v1.z, v1.w};
            float f2[4] = {v2.x, v2.y, v2.z, v2.w};
            float f3[4] = {v3.x, v3.y, v3.z, v3.w};
            #pragma unroll
            for (int e = 0; e < 4; ++e) {
                const int idx = base + e;
                const int j = idx / 3;
                const int k = idx - j * 3;
                smb[k    ][j] = make_float2(-f1[e], -f1[e]);  // negated A
                smb[3 + k][j] = make_float2( f2[e],  f2[e]);
                smb[6 + k][j] = make_float2( f3[e],  f3[e]);
            }
        }
        if (threadIdx.x < 48) sp[threadIdx.x] = xyz[pbase * 3 + threadIdx.x];
    }
    __syncthreads();

    const int chunk = threadIdx.x & 31;
    const int grp   = threadIdx.x >> 5;   // 0..3, 4 points each

    // 2 packed point pairs
    ull PPX[2], PPY[2], PPZ[2];
    float bestD[4];
    int   bestT[4];
    #pragma unroll
    for (int pr = 0; pr < 2; ++pr) {
        const int p0 = (grp * 4 + 2 * pr) * 3;
        PPX[pr] = pk2(sp[p0 + 0], sp[p0 + 3]);
        PPY[pr] = pk2(sp[p0 + 1], sp[p0 + 4]);
        PPZ[pr] = pk2(sp[p0 + 2], sp[p0 + 5]);
    }
    #pragma unroll
    for (int k = 0; k < 4; ++k) { bestD[k] = INFINITY; bestT[k] = 0x7fffffff; }

    const ull N1 = pk2(-1.f, -1.f);

    #pragma unroll 1
    for (int j = 0; j < 16; ++j) {
        const int t = j * 32 + chunk;

        // 9 broadcast LDS.64 loads
        const ull NAX = *reinterpret_cast<const ull*>(&smb[0][t]);
        const ull NAY = *reinterpret_cast<const ull*>(&smb[1][t]);
        const ull NAZ = *reinterpret_cast<const ull*>(&smb[2][t]);
        const ull BXP = *reinterpret_cast<const ull*>(&smb[3][t]);
        const ull BYP = *reinterpret_cast<const ull*>(&smb[4][t]);
        const ull BZP = *reinterpret_cast<const ull*>(&smb[5][t]);
        const ull CXP = *reinterpret_cast<const ull*>(&smb[6][t]);
        const ull CYP = *reinterpret_cast<const ull*>(&smb[7][t]);
        const ull CZP = *reinterpret_cast<const ull*>(&smb[8][t]);

        // packed per-triangle setup (broadcast-identical lanes)
        const ull ABX = add2_(BXP, NAX);
        const ull ABY = add2_(BYP, NAY);
        const ull ABZ = add2_(BZP, NAZ);
        const ull ACX = add2_(CXP, NAX);
        const ull ACY = add2_(CYP, NAY);
        const ull ACZ = add2_(CZP, NAZ);
        const ull E1P = fma2_(ABX, ABX, fma2_(ABY, ABY, mul2_(ABZ, ABZ)));
        const ull E2P = fma2_(ABX, ACX, fma2_(ABY, ACY, mul2_(ABZ, ACZ)));
        const ull E3P = fma2_(ACX, ACX, fma2_(ACY, ACY, mul2_(ACZ, ACZ)));
        const ull NE2 = mul2_(E2P, N1);
        const ull F1P = add2_(E1P, NE2);
        const ull F2P = add2_(E3P, NE2);
        const ull CB2 = add2_(F1P, F2P);
        const ull DNP = fma2_(E2P, NE2, mul2_(E1P, E3P));

        // scalar reciprocals (lanes identical -> compute on lo, repack)
        const float rdn = frcp(lo2(DNP));
        const ull RDNP  = pk2( rdn,  rdn);
        const ull NRDNP = pk2(-rdn, -rdn);
        const float e1r = frcp(lo2(E1P));
        const float e3r = frcp(lo2(E3P));
        const float cbr = frcp(lo2(CB2));
        const ull NRE1 = pk2(-e1r, -e1r);
        const ull NRE3 = pk2(-e3r, -e3r);
        const ull NRCB = pk2(-cbr, -cbr);
        const ull Q1P = mul2_(E3P, NRDNP);
        const ull Q2P = mul2_(E2P, RDNP);
        const ull Q3P = mul2_(E1P, NRDNP);

        #pragma unroll
        for (int pr = 0; pr < 2; ++pr) {
            const ull APX = add2_(PPX[pr], NAX);
            const ull APY = add2_(PPY[pr], NAY);
            const ull APZ = add2_(PPZ[pr], NAZ);

            const ull D1 = fma2_(ABX, APX, fma2_(ABY, APY, mul2_(ABZ, APZ)));
            const ull D2 = fma2_(ACX, APX, fma2_(ACY, APY, mul2_(ACZ, APZ)));

            // --- segment AB ---  tn = clamp(d1*(-1/e1), -1, 0)
            ull TN = clampn2(mul2_(D1, NRE1));
            ull DX = fma2_(ABX, TN, APX);
            ull DY = fma2_(ABY, TN, APY);
            ull DZ = fma2_(ABZ, TN, APZ);
            const ull DAB = fma2_(DX, DX, fma2_(DY, DY, mul2_(DZ, DZ)));

            // --- segment AC ---
            TN = clampn2(mul2_(D2, NRE3));
            DX = fma2_(ACX, TN, APX);
            DY = fma2_(ACY, TN, APY);
            DZ = fma2_(ACZ, TN, APZ);
            const ull DAC = fma2_(DX, DX, fma2_(DY, DY, mul2_(DZ, DZ)));

            // --- segment BC ---  u1 = (d2-d1)+f1; a-origin form:
            //   diff = ap + TN*ac + TM*ab,  TM = -1 - TN
            const ull U1 = add2_(fma2_(D1, N1, D2), F1P);
            TN = clampn2(mul2_(U1, NRCB));
            const ull TM = fma2_(TN, N1, N1);
            DX = fma2_(ABX, TM, fma2_(ACX, TN, APX));
            DY = fma2_(ABY, TM, fma2_(ACY, TN, APY));
            DZ = fma2_(ABZ, TM, fma2_(ACZ, TN, APZ));
            const ull DBC = fma2_(DX, DX, fma2_(DY, DY, mul2_(DZ, DZ)));

            // --- face ---  nv = -v = d1*q1 + d2*q2 ; nw = -w = d2*q3 + d1*q2
            const ull NV = fma2_(D1, Q1P, mul2_(D2, Q2P));
            const ull NW = fma2_(D2, Q3P, mul2_(D1, Q2P));
            const ull SS = add2_(NV, NW);   // -(v+w)
            DX = fma2_(ABX, NV, fma2_(ACX, NW, APX));
            DY = fma2_(ABY, NV, fma2_(ACY, NW, APY));
            DZ = fma2_(ABZ, NV, fma2_(ACZ, NW, APZ));
            const ull DF = fma2_(DX, DX, fma2_(DY, DY, mul2_(DZ, DZ)));

            // --- per-component resolve ---
            float nv0, nv1, nw0, nw1, ss0, ss1, df0, df1;
            float a0, a1, c0, c1, b0, b1;
            up2(NV, nv0, nv1); up2(NW, nw0, nw1); up2(SS, ss0, ss1);
            up2(DF, df0, df1);
            up2(DAB, a0, a1); up2(DAC, c0, c1); up2(DBC, b0, b1);

            float d0  = fminf(fminf(a0, c0), b0);
            float d1v = fminf(fminf(a1, c1), b1);
            // inside <=> v>=0, w>=0, v+w<=1  <=> nv<=0, nw<=0, ss>=-1
            // (NaN -> comparisons false -> face excluded)
            if (fmaxf(nv0, nw0) <= 0.f && ss0 >= -1.f) d0  = fminf(d0,  df0);
            if (fmaxf(nv1, nw1) <= 0.f && ss1 >= -1.f) d1v = fminf(d1v, df1);

            const int k0 = 2 * pr;
            if (d0  < bestD[k0])     { bestD[k0]     = d0;  bestT[k0]     = t; }
            if (d1v < bestD[k0 + 1]) { bestD[k0 + 1] = d1v; bestT[k0 + 1] = t; }
        }
    }

    // Lexicographic (dist, index) butterfly reduction across the 32 chunks.
    #pragma unroll
    for (int off = 1; off < 32; off <<= 1) {
        #pragma unroll
        for (int k = 0; k < 4; ++k) {
            float dO = __shfl_xor_sync(0xffffffffu, bestD[k], off);
            int   tO = __shfl_xor_sync(0xffffffffu, bestT[k], off);
            if (dO < bestD[k] || (dO == bestD[k] && tO < bestT[k])) {
                bestD[k] = dO;
                bestT[k] = tO;
            }
        }
    }

    if (chunk == 0) {
        #pragma unroll
        for (int k = 0; k < 4; ++k) {
            const int g = pbase + grp * 4 + k;
            const int t = bestT[k];
            const float px = sp[(grp * 4 + k) * 3 + 0];
            const float py = sp[(grp * 4 + k) * 3 + 1];
            const float pz = sp[(grp * 4 + k) * 3 + 2];
            const int r = region_of(px, py, pz,
                                    -smb[0][t].x, -smb[1][t].x, -smb[2][t].x,
                                     smb[3][t].x,  smb[4][t].x,  smb[5][t].x,
                                     smb[6][t].x,  smb[7][t].x,  smb[8][t].x);
            out[g]          = bestD[k];
            out[BN + g]     = (float)r;
            out[2 * BN + g] = (float)t;
        }
    }
}

extern "C" void kernel_launch(void* const* d_in, const int* in_sizes, int n_in,
                              void* d_out, int out_size)
{
    const float* xyz  = (const float*)d_in[0];
    const float* tri1 = (const float*)d_in[1];
    const float* tri2 = (const float*)d_in[2];
    const float* tri3 = (const float*)d_in[3];
    float* out = (float*)d_out;

    dim3 grid(BN / 16);   // 1024 CTAs
    dim3 block(128);
    tridist_kernel<<<grid, block>>>(xyz, tri1, tri2, tri3, out);
}

// round 14
// speedup vs baseline: 1.1105x; 1.1105x over previous
#include <cuda_runtime.h>
#include <math.h>

// Problem constants: B=4, n=4096 points, m=512 triangles.
#define BATCH 4
#define NPTS  4096
#define MTRI  512
#define BN    (BATCH * NPTS)   // 16384

// Decomposition (round-12 winner + one-wave residency):
//   128-thread CTAs (4 warps), 16 points/CTA, grid = 1024.
//   chunk = tid & 31 (32 triangle chunks), grp = tid >> 5 (4 groups x 4 pts).
//   Each thread: 4 points = 2 packed f32x2 pairs x 16 triangles.
// __launch_bounds__(128, 7): 73-reg budget -> 7 CTAs/SM -> 1036 concurrent
//   CTAs >= 1024 grid -> ENTIRE GRID IN ONE WAVE, 28 warps/SM.
//   (reg cuts vs round 12: packed SS removed -> scalar adds; rdn dies early.)
//
// Packed-pair candidate-min evaluation (fma.rn.f32x2 path):
//   dist^2 = min(seg_ab, seg_ac, seg_bc, inside ? face : +inf)
//  - BC segment on the a-origin: diff = ap + TN*ac + TM*ab, TM = -1-TN.
//  - face: -v = d1*q1 + d2*q2, -w = d2*q3 + d1*q2 with scalar pre-divided
//    q1=-e3/dn, q2=e2/dn, q3=-e1/dn; inside <=> max(-v,-w)<=0 && -(v+w)>=-1.
// Region code recomputed reference-exactly for the winning triangle only.

typedef unsigned long long ull;

__device__ __forceinline__ ull pk2(float lo, float hi) {
    ull r;
    asm("mov.b64 %0, {%1, %2};" : "=l"(r) : "f"(lo), "f"(hi));
    return r;
}
__device__ __forceinline__ void up2(ull v, float& lo, float& hi) {
    asm("mov.b64 {%0, %1}, %2;" : "=f"(lo), "=f"(hi) : "l"(v));
}
__device__ __forceinline__ ull fma2_(ull a, ull b, ull c) {
    ull r;
    asm("fma.rn.f32x2 %0, %1, %2, %3;" : "=l"(r) : "l"(a), "l"(b), "l"(c));
    return r;
}
__device__ __forceinline__ ull mul2_(ull a, ull b) {
    ull r;
    asm("mul.rn.f32x2 %0, %1, %2;" : "=l"(r) : "l"(a), "l"(b));
    return r;
}
__device__ __forceinline__ ull add2_(ull a, ull b) {
    ull r;
    asm("add.rn.f32x2 %0, %1, %2;" : "=l"(r) : "l"(a), "l"(b));
    return r;
}
__device__ __forceinline__ float frcp(float x) {
    float r;
    asm("rcp.approx.f32 %0, %1;" : "=f"(r) : "f"(x));
    return r;
}
// clamp both components of a packed value to [-1, 0]
__device__ __forceinline__ ull clampn2(ull v) {
    float lo, hi;
    up2(v, lo, hi);
    lo = fminf(fmaxf(lo, -1.f), 0.f);
    hi = fminf(fmaxf(hi, -1.f), 0.f);
    return pk2(lo, hi);
}

__device__ int region_of(float px, float py, float pz,
                         float ax, float ay, float az,
                         float bx, float by, float bz,
                         float cx, float cy, float cz)
{
    const float abx = bx - ax, aby = by - ay, abz = bz - az;
    const float acx = cx - ax, acy = cy - ay, acz = cz - az;
    const float apx = px - ax, apy = py - ay, apz = pz - az;
    const float bpx = px - bx, bpy = py - by, bpz = pz - bz;
    const float cpx = px - cx, cpy = py - cy, cpz = pz - cz;
    const float d1 = abx * apx + aby * apy + abz * apz;
    const float d2 = acx * apx + acy * apy + acz * apz;
    const float d3 = abx * bpx + aby * bpy + abz * bpz;
    const float d4 = acx * bpx + acy * bpy + acz * bpz;
    const float d5 = abx * cpx + aby * cpy + abz * cpz;
    const float d6 = acx * cpx + acy * cpy + acz * cpz;
    const float vc = d1 * d4 - d3 * d2;
    const float vb = d5 * d2 - d1 * d6;
    const float va = d3 * d6 - d5 * d4;
    if (d1 <= 0.f && d2 <= 0.f) return 0;
    if (d3 >= 0.f && d4 <= d3) return 1;
    if (vc <= 0.f && d1 >= 0.f && d3 <= 0.f) return 3;
    if (d6 >= 0.f && d5 <= d6) return 2;
    if (vb <= 0.f && d2 >= 0.f && d6 <= 0.f) return 4;
    if (va <= 0.f && (d4 - d3) >= 0.f && (d5 - d6) >= 0.f) return 5;
    return 6;
}

__global__ void __launch_bounds__(128, 7)
tridist_kernel(const float* __restrict__ xyz,
               const float* __restrict__ tri1,
               const float* __restrict__ tri2,
               const float* __restrict__ tri3,
               float* __restrict__ out)
{
    __shared__ float sm[9][MTRI];   // ax ay az bx by bz cx cy cz  (SoA)
    __shared__ float sp[48];        // 16 points * 3

    const int b     = blockIdx.x >> 8;
    const int blk   = blockIdx.x & 255;
    const int pbase = b * NPTS + blk * 16;

    // Stage triangles (float4 loads, SoA scatter into smem).
    {
        const float4* t1 = (const float4*)(tri1 + b * MTRI * 3);
        const float4* t2 = (const float4*)(tri2 + b * MTRI * 3);
        const float4* t3 = (const float4*)(tri3 + b * MTRI * 3);
        #pragma unroll
        for (int it = 0; it < 3; ++it) {
            const int i4 = it * 128 + threadIdx.x;   // 0..383
            float4 v1 = t1[i4], v2 = t2[i4], v3 = t3[i4];
            const int base = i4 * 4;
            float f1[4] = {v1.x, v1.y, v1.z, v1.w};
            float f2[4] = {v2.x, v2.y, v2.z, v2.w};
            float f3[4] = {v3.x, v3.y, v3.z, v3.w};
            #pragma unroll
            for (int e = 0; e < 4; ++e) {
                const int idx = base + e;
                const int j = idx / 3;
                const int k = idx - j * 3;
                sm[k    ][j] = f1[e];
                sm[3 + k][j] = f2[e];
                sm[6 + k][j] = f3[e];
            }
        }
        if (threadIdx.x < 48) sp[threadIdx.x] = xyz[pbase * 3 + threadIdx.x];
    }
    __syncthreads();

    const int chunk = threadIdx.x & 31;
    const int grp   = threadIdx.x >> 5;   // 0..3, 4 points each

    // 2 packed point pairs
    ull PPX[2], PPY[2], PPZ[2];
    float bestD[4];
    int   bestT[4];
    #pragma unroll
    for (int pr = 0; pr < 2; ++pr) {
        const int p0 = (grp * 4 + 2 * pr) * 3;
        PPX[pr] = pk2(sp[p0 + 0], sp[p0 + 3]);
        PPY[pr] = pk2(sp[p0 + 1], sp[p0 + 4]);
        PPZ[pr] = pk2(sp[p0 + 2], sp[p0 + 5]);
    }
    #pragma unroll
    for (int k = 0; k < 4; ++k) { bestD[k] = INFINITY; bestT[k] = 0x7fffffff; }

    const ull N1 = pk2(-1.f, -1.f);

    #pragma unroll 1
    for (int j = 0; j < 16; ++j) {
        const int t = j * 32 + chunk;

        const float ax = sm[0][t], ay = sm[1][t], az = sm[2][t];
        const float bx = sm[3][t], by = sm[4][t], bz = sm[5][t];
        const float cx = sm[6][t], cy = sm[7][t], cz = sm[8][t];

        // scalar per-triangle setup
        const float abx = bx - ax, aby = by - ay, abz = bz - az;
        const float acx = cx - ax, acy = cy - ay, acz = cz - az;
        const float e1 = fmaf(abx, abx, fmaf(aby, aby, abz * abz));
        const float e2 = fmaf(abx, acx, fmaf(aby, acy, abz * acz));
        const float e3 = fmaf(acx, acx, fmaf(acy, acy, acz * acz));
        const float f1s = e1 - e2;
        const float f2s = e3 - e2;
        const float cb2 = f1s + f2s;                    // |cb|^2
        const float denom = fmaf(e1, e3, -(e2 * e2));   // |ab x ac|^2
        const float rdn  = frcp(denom);                 // dies after q's
        const float q1s  = -e3 * rdn;
        const float q2s  =  e2 * rdn;
        const float q3s  = -e1 * rdn;
        const float nre1 = -frcp(e1);
        const float nre3 = -frcp(e3);
        const float nrcb = -frcp(cb2);

        // packed broadcast constants (amortized over 2 pairs)
        const ull NAX = pk2(-ax, -ax), NAY = pk2(-ay, -ay), NAZ = pk2(-az, -az);
        const ull ABX = pk2(abx, abx), ABY = pk2(aby, aby), ABZ = pk2(abz, abz);
        const ull ACX = pk2(acx, acx), ACY = pk2(acy, acy), ACZ = pk2(acz, acz);
        const ull F1P = pk2(f1s, f1s);
        const ull NRE1 = pk2(nre1, nre1), NRE3 = pk2(nre3, nre3);
        const ull NRCB = pk2(nrcb, nrcb);
        const ull Q1P = pk2(q1s, q1s), Q2P = pk2(q2s, q2s), Q3P = pk2(q3s, q3s);

        #pragma unroll
        for (int pr = 0; pr < 2; ++pr) {
            const ull APX = add2_(PPX[pr], NAX);
            const ull APY = add2_(PPY[pr], NAY);
            const ull APZ = add2_(PPZ[pr], NAZ);

            const ull D1 = fma2_(ABX, APX, fma2_(ABY, APY, mul2_(ABZ, APZ)));
            const ull D2 = fma2_(ACX, APX, fma2_(ACY, APY, mul2_(ACZ, APZ)));

            // --- segment AB ---  tn = clamp(d1*(-1/e1), -1, 0)
            ull TN = clampn2(mul2_(D1, NRE1));
            ull DX = fma2_(ABX, TN, APX);
            ull DY = fma2_(ABY, TN, APY);
            ull DZ = fma2_(ABZ, TN, APZ);
            const ull DAB = fma2_(DX, DX, fma2_(DY, DY, mul2_(DZ, DZ)));

            // --- segment AC ---
            TN = clampn2(mul2_(D2, NRE3));
            DX = fma2_(ACX, TN, APX);
            DY = fma2_(ACY, TN, APY);
            DZ = fma2_(ACZ, TN, APZ);
            const ull DAC = fma2_(DX, DX, fma2_(DY, DY, mul2_(DZ, DZ)));

            // --- segment BC ---  u1 = (d2-d1)+f1; a-origin form:
            //   diff = ap + TN*ac + TM*ab,  TM = -1 - TN
            const ull U1 = add2_(fma2_(D1, N1, D2), F1P);
            TN = clampn2(mul2_(U1, NRCB));
            const ull TM = fma2_(TN, N1, N1);
            DX = fma2_(ABX, TM, fma2_(ACX, TN, APX));
            DY = fma2_(ABY, TM, fma2_(ACY, TN, APY));
            DZ = fma2_(ABZ, TM, fma2_(ACZ, TN, APZ));
            const ull DBC = fma2_(DX, DX, fma2_(DY, DY, mul2_(DZ, DZ)));

            // --- face ---  nv = -v = d1*q1 + d2*q2 ; nw = -w = d2*q3 + d1*q2
            const ull NV = fma2_(D1, Q1P, mul2_(D2, Q2P));
            const ull NW = fma2_(D2, Q3P, mul2_(D1, Q2P));
            DX = fma2_(ABX, NV, fma2_(ACX, NW, APX));
            DY = fma2_(ABY, NV, fma2_(ACY, NW, APY));
            DZ = fma2_(ABZ, NV, fma2_(ACZ, NW, APZ));
            const ull DF = fma2_(DX, DX, fma2_(DY, DY, mul2_(DZ, DZ)));

            // --- per-component resolve (ss computed scalar: saves regs) ---
            float nv0, nv1, nw0, nw1, df0, df1;
            float a0, a1, c0, c1, b0, b1;
            up2(NV, nv0, nv1); up2(NW, nw0, nw1);
            up2(DF, df0, df1);
            up2(DAB, a0, a1); up2(DAC, c0, c1); up2(DBC, b0, b1);

            float d0  = fminf(fminf(a0, c0), b0);
            float d1v = fminf(fminf(a1, c1), b1);
            // inside <=> v>=0, w>=0, v+w<=1  <=> nv<=0, nw<=0, nv+nw>=-1
            // (NaN -> comparisons false -> face excluded)
            if (fmaxf(nv0, nw0) <= 0.f && (nv0 + nw0) >= -1.f) d0  = fminf(d0,  df0);
            if (fmaxf(nv1, nw1) <= 0.f && (nv1 + nw1) >= -1.f) d1v = fminf(d1v, df1);

            const int k0 = 2 * pr;
            if (d0  < bestD[k0])     { bestD[k0]     = d0;  bestT[k0]     = t; }
            if (d1v < bestD[k0 + 1]) { bestD[k0 + 1] = d1v; bestT[k0 + 1] = t; }
        }
    }

    // Lexicographic (dist, index) butterfly reduction across the 32 chunks.
    #pragma unroll
    for (int off = 1; off < 32; off <<= 1) {
        #pragma unroll
        for (int k = 0; k < 4; ++k) {
            float dO = __shfl_xor_sync(0xffffffffu, bestD[k], off);
            int   tO = __shfl_xor_sync(0xffffffffu, bestT[k], off);
            if (dO < bestD[k] || (dO == bestD[k] && tO < bestT[k])) {
                bestD[k] = dO;
                bestT[k] = tO;
            }
        }
    }

    if (chunk == 0) {
        #pragma unroll
        for (int k = 0; k < 4; ++k) {
            const int g = pbase + grp * 4 + k;
            const int t = bestT[k];
            const float px = sp[(grp * 4 + k) * 3 + 0];
            const float py = sp[(grp * 4 + k) * 3 + 1];
            const float pz = sp[(grp * 4 + k) * 3 + 2];
            const int r = region_of(px, py, pz,
                                    sm[0][t], sm[1][t], sm[2][t],
                                    sm[3][t], sm[4][t], sm[5][t],
                                    sm[6][t], sm[7][t], sm[8][t]);
            out[g]          = bestD[k];
            out[BN + g]     = (float)r;
            out[2 * BN + g] = (float)t;
        }
    }
}

extern "C" void kernel_launch(void* const* d_in, const int* in_sizes, int n_in,
                              void* d_out, int out_size)
{
    const float* xyz  = (const float*)d_in[0];
    const float* tri1 = (const float*)d_in[1];
    const float* tri2 = (const float*)d_in[2];
    const float* tri3 = (const float*)d_in[3];
    float* out = (float*)d_out;

    dim3 grid(BN / 16);   // 1024 CTAs
    dim3 block(128);
    tridist_kernel<<<grid, block>>>(xyz, tri1, tri2, tri3, out);
}